// round 16
// baseline (speedup 1.0000x reference)
#include <cuda_runtime.h>
#include <cstdint>

#define BB 4
#define LL 512
#define DD 768
#define DOUT 384
#define KSEL 51
#define NROW (BB*LL)
#define NSPLIT 64
#define GEMM_BLOCKS 384   // 24 x 16

// ---- device scratch ----
__device__ float g_fsrc[NROW * DD];
__device__ float g_fdst[NROW * DD];
__device__ float g_h[NROW * DD];
__device__ int   g_idx[NROW * KSEL];
__device__ float g_gate[NROW];
__device__ unsigned g_gmax[BB];
__device__ float g_part[BB * NSPLIT * DD];
__device__ float g_partz[BB * NSPLIT];

__device__ __forceinline__ unsigned fenc(float f) {
    unsigned u = __float_as_uint(f);
    return (u & 0x80000000u) ? ~u : (u | 0x80000000u);
}
__device__ __forceinline__ float fdec(unsigned u) {
    unsigned b = (u & 0x80000000u) ? (u & 0x7FFFFFFFu) : ~u;
    return __uint_as_float(b);
}

// ============================================================
// Fused GEMM + Top-K kernel. 256 threads.
//   blockIdx.x < 384  : tf32 GEMM (cp.async 3-stage, BM128 BN64 BK32)
//   blockIdx.x >= 384 : top-K radix select for row = blockIdx.x - 384
// Independent inputs; topk blocks fill the GEMM's idle issue slots.
// ============================================================
#define GNIT 24
#define SA_ST 4608               // 128*36 floats per stage
#define SB_ST 2304               // 32*72 floats per stage
#define GEMM_SMEM ((3*SA_ST + 3*SB_ST) * 4)

__device__ __forceinline__ void cp16(float* sdst, const float* gsrc) {
    uint32_t s = (uint32_t)__cvta_generic_to_shared(sdst);
    asm volatile("cp.async.cg.shared.global [%0], [%1], 16;\n" :: "r"(s), "l"(gsrc));
}
__device__ __forceinline__ void mma_tf32(float* d, const uint32_t* a, const uint32_t* b) {
    asm volatile(
        "mma.sync.aligned.m16n8k8.row.col.f32.tf32.tf32.f32 "
        "{%0,%1,%2,%3}, {%4,%5,%6,%7}, {%8,%9}, {%0,%1,%2,%3};\n"
        : "+f"(d[0]), "+f"(d[1]), "+f"(d[2]), "+f"(d[3])
        : "r"(a[0]), "r"(a[1]), "r"(a[2]), "r"(a[3]), "r"(b[0]), "r"(b[1]));
}

__global__ __launch_bounds__(256) void gemm_topk_kernel(
    const float* __restrict__ A,
    const float* __restrict__ Wsrc, const float* __restrict__ bsrc,
    const float* __restrict__ Wdst, const float* __restrict__ bdst,
    const float* __restrict__ attn) {
    extern __shared__ float gsm[];
    int tid = threadIdx.x;

    if (blockIdx.x < GEMM_BLOCKS) {
        // ---------------- GEMM branch ----------------
        float* sAp = gsm;
        float* sBp = gsm + 3 * SA_ST;

        int gx = blockIdx.x % 24;
        int gy = blockIdx.x / 24;
        int colBase = gx * 64;
        int rowBase = gy * 128;

        const float *W, *bias;
        float* Cout;
        int cb;
        if (colBase < DD) { W = Wsrc; bias = bsrc; Cout = g_fsrc; cb = colBase; }
        else              { W = Wdst; bias = bdst; Cout = g_fdst; cb = colBase - DD; }

        int lane = tid & 31, wid = tid >> 5;
        int warpM = wid & 3, warpN = wid >> 2;
        int g = lane >> 2, t4 = lane & 3;

        int ar[4], ac[4];
#pragma unroll
        for (int q = 0; q < 4; q++) { int i = tid + q * 256; ar[q] = i >> 3; ac[q] = (i & 7) * 4; }
        int br[2], bc[2];
#pragma unroll
        for (int q = 0; q < 2; q++) { int i = tid + q * 256; br[q] = i >> 4; bc[q] = (i & 15) * 4; }

        float acc[2][4][4];
#pragma unroll
        for (int i = 0; i < 2; i++)
#pragma unroll
            for (int j = 0; j < 4; j++)
#pragma unroll
                for (int q = 0; q < 4; q++) acc[i][j][q] = 0.f;

#define GISSUE(it)                                                              \
    do {                                                                        \
        if ((it) < GNIT) {                                                      \
            int k0 = (it) * 32; int st = (it) % 3;                              \
            float* sA = sAp + st * SA_ST;                                       \
            float* sB = sBp + st * SB_ST;                                       \
            _Pragma("unroll")                                                   \
            for (int q = 0; q < 4; q++)                                         \
                cp16(&sA[ar[q] * 36 + ac[q]],                                   \
                     &A[(size_t)(rowBase + ar[q]) * DD + k0 + ac[q]]);          \
            _Pragma("unroll")                                                   \
            for (int q = 0; q < 2; q++)                                         \
                cp16(&sB[br[q] * 72 + bc[q]],                                   \
                     &W[(size_t)(k0 + br[q]) * DD + cb + bc[q]]);               \
        }                                                                       \
        asm volatile("cp.async.commit_group;\n" ::);                            \
    } while (0)

        GISSUE(0);
        GISSUE(1);

        for (int it = 0; it < GNIT; it++) {
            asm volatile("cp.async.wait_group 1;\n" ::);
            __syncthreads();
            GISSUE(it + 2);

            int st = it % 3;
            const float* sA = sAp + st * SA_ST;
            const float* sB = sBp + st * SB_ST;
#pragma unroll
            for (int kk = 0; kk < 4; kk++) {
                int kb = kk * 8;
                uint32_t af[2][4], bf[4][2];
#pragma unroll
                for (int i = 0; i < 2; i++) {
                    int m0 = warpM * 32 + i * 16;
                    af[i][0] = __float_as_uint(sA[(m0 + g) * 36 + kb + t4]);
                    af[i][1] = __float_as_uint(sA[(m0 + g + 8) * 36 + kb + t4]);
                    af[i][2] = __float_as_uint(sA[(m0 + g) * 36 + kb + t4 + 4]);
                    af[i][3] = __float_as_uint(sA[(m0 + g + 8) * 36 + kb + t4 + 4]);
                }
#pragma unroll
                for (int j = 0; j < 4; j++) {
                    int n0 = warpN * 32 + j * 8 + g;
                    bf[j][0] = __float_as_uint(sB[(kb + t4) * 72 + n0]);
                    bf[j][1] = __float_as_uint(sB[(kb + t4 + 4) * 72 + n0]);
                }
#pragma unroll
                for (int i = 0; i < 2; i++)
#pragma unroll
                    for (int j = 0; j < 4; j++)
                        mma_tf32(acc[i][j], af[i], bf[j]);
            }
        }

#pragma unroll
        for (int i = 0; i < 2; i++) {
            int r0 = rowBase + warpM * 32 + i * 16 + g;
#pragma unroll
            for (int j = 0; j < 4; j++) {
                int c0 = cb + warpN * 32 + j * 8 + t4 * 2;
                float b0 = bias[c0], b1 = bias[c0 + 1];
                Cout[(size_t)r0 * DD + c0]           = acc[i][j][0] + b0;
                Cout[(size_t)r0 * DD + c0 + 1]       = acc[i][j][1] + b1;
                Cout[(size_t)(r0 + 8) * DD + c0]     = acc[i][j][2] + b0;
                Cout[(size_t)(r0 + 8) * DD + c0 + 1] = acc[i][j][3] + b1;
            }
        }
    } else {
        // ---------------- Top-K branch (256 threads, 2 elems/thread) ----------------
        __shared__ unsigned su[LL];
        __shared__ int hist[256];
        __shared__ int suf[256];
        __shared__ unsigned s_prefix;
        __shared__ int s_need;
        __shared__ int s_cnt;

        int row = blockIdx.x - GEMM_BLOCKS;
        int t = tid;
        if (row < BB && t == 0) g_gmax[row] = 0u;
        unsigned u0 = __float_as_uint(attn[(size_t)row * LL + t]);
        unsigned u1 = __float_as_uint(attn[(size_t)row * LL + t + 256]);
        su[t] = u0;
        su[t + 256] = u1;
        if (t == 0) { s_prefix = 0u; s_need = KSEL; s_cnt = 0; }
        unsigned himask = 0u;
        __syncthreads();

#pragma unroll
        for (int shift = 24; shift >= 0; shift -= 8) {
            unsigned pref = s_prefix;
            int need = s_need;
            hist[t] = 0;
            __syncthreads();

            if ((u0 & himask) == pref) atomicAdd(&hist[(u0 >> shift) & 0xFF], 1);
            if ((u1 & himask) == pref) atomicAdd(&hist[(u1 >> shift) & 0xFF], 1);
            __syncthreads();

            if (t < 32) {
                int v[8];
                int base = t * 8;
                int sum = 0;
#pragma unroll
                for (int i = 7; i >= 0; i--) { sum += hist[base + i]; v[i] = sum; }
                int x = sum;
#pragma unroll
                for (int off = 1; off < 32; off <<= 1) {
                    int y = __shfl_down_sync(0xffffffffu, x, off);
                    if (t + off < 32) x += y;
                }
                int excl = x - sum;
#pragma unroll
                for (int i = 0; i < 8; i++) suf[base + i] = v[i] + excl;
            }
            __syncthreads();
            {
                int above = (t + 1 < 256) ? suf[t + 1] : 0;
                if (suf[t] >= need && above < need) {
                    s_need = need - above;
                    s_prefix = pref | ((unsigned)t << shift);
                }
            }
            himask |= (0xFFu << shift);
            __syncthreads();
        }

        unsigned T = s_prefix;
        int need = s_need;
        if (u0 > T) {
            int slot = atomicAdd(&s_cnt, 1);
            g_idx[row * KSEL + slot] = t;
        }
        if (u1 > T) {
            int slot = atomicAdd(&s_cnt, 1);
            g_idx[row * KSEL + slot] = t + 256;
        }
        __syncthreads();
        int ngt = s_cnt;
        if (u0 == T) {
            int r = 0;
            for (int j = 0; j < t; j++) r += (su[j] == T);
            if (r < need) g_idx[row * KSEL + ngt + r] = t;
        }
        if (u1 == T) {
            int r = 0;
            for (int j = 0; j < t + 256; j++) r += (su[j] == T);
            if (r < need) g_idx[row * KSEL + ngt + r] = t + 256;
        }
    }
}

// ============================================================
// Edge kernel: barrier-free warp-local online softmax with
// buffered tree merge (round-15 proven version, unchanged).
// ============================================================
__global__ __launch_bounds__(256, 2) void edge_kernel(
    const float* __restrict__ attn, const float* __restrict__ hidden,
    const float* __restrict__ attn_vec, const float* __restrict__ gat_bias,
    const float* __restrict__ gate_W, const float* __restrict__ gate_b) {
    __shared__ float s_av[DD];
    __shared__ float s_buf[8][DD];
    __shared__ int   ik[KSEL];
    __shared__ float aval[KSEL];
    __shared__ float s_m[8];
    __shared__ float s_Z[8];
    __shared__ float red8[8];

    int row = blockIdx.x;
    int b = row >> 9;
    int t = threadIdx.x;
    int warp = t >> 5, lane = t & 31;

    if (t < KSEL) {
        int idx = g_idx[row * KSEL + t];
        ik[t] = idx;
        aval[t] = attn[(size_t)row * LL + idx];
    }
    s_av[t] = attn_vec[t];
    s_av[t + 256] = attn_vec[t + 256];
    s_av[t + 512] = attn_vec[t + 512];

    float4 fd[6];
#pragma unroll
    for (int j = 0; j < 6; j++)
        fd[j] = *(const float4*)&g_fdst[(size_t)row * DD + 4 * lane + 128 * j];
    __syncthreads();

    const float* fsb = &g_fsrc[(size_t)b * LL * DD];

    float m = -1e30f, Z = 0.f;
    float4 acc[6];
#pragma unroll
    for (int j = 0; j < 6; j++) acc[j] = make_float4(0.f, 0.f, 0.f, 0.f);

    float4 cf[6];
    {
        const float* fs = fsb + (size_t)ik[warp] * DD;
#pragma unroll
        for (int j = 0; j < 6; j++)
            cf[j] = *(const float4*)&fs[4 * lane + 128 * j];
    }

    for (int k = warp; k < KSEL; k += 8) {
        float4 nf[6];
        bool more = (k + 8) < KSEL;
        if (more) {
            const float* fs = fsb + (size_t)ik[k + 8] * DD;
#pragma unroll
            for (int j = 0; j < 6; j++)
                nf[j] = *(const float4*)&fs[4 * lane + 128 * j];
        }

        float p = 0.f;
#pragma unroll
        for (int j = 0; j < 6; j++) {
            float4 a = *(const float4*)&s_av[4 * lane + 128 * j];
            float x;
            x = cf[j].x + fd[j].x; x = x > 0.f ? x : 0.2f * x; p += x * a.x;
            x = cf[j].y + fd[j].y; x = x > 0.f ? x : 0.2f * x; p += x * a.y;
            x = cf[j].z + fd[j].z; x = x > 0.f ? x : 0.2f * x; p += x * a.z;
            x = cf[j].w + fd[j].w; x = x > 0.f ? x : 0.2f * x; p += x * a.w;
        }
#pragma unroll
        for (int o = 16; o > 0; o >>= 1) p += __shfl_xor_sync(0xffffffffu, p, o);
        float s = (aval[k] > 0.f) ? p : -1e9f;

        if (s <= m) {
            float e = expf(s - m);
            Z += e;
#pragma unroll
            for (int j = 0; j < 6; j++) {
                acc[j].x += e * cf[j].x; acc[j].y += e * cf[j].y;
                acc[j].z += e * cf[j].z; acc[j].w += e * cf[j].w;
            }
        } else {
            float sc = expf(m - s);
            Z = Z * sc + 1.f;
#pragma unroll
            for (int j = 0; j < 6; j++) {
                acc[j].x = acc[j].x * sc + cf[j].x; acc[j].y = acc[j].y * sc + cf[j].y;
                acc[j].z = acc[j].z * sc + cf[j].z; acc[j].w = acc[j].w * sc + cf[j].w;
            }
            m = s;
        }
        if (more) {
#pragma unroll
            for (int j = 0; j < 6; j++) cf[j] = nf[j];
        }
    }

    if (lane == 0) { s_m[warp] = m; s_Z[warp] = Z; }
    __syncthreads();

    float mstar = s_m[0];
#pragma unroll
    for (int w = 1; w < 8; w++) mstar = fmaxf(mstar, s_m[w]);
    float Zt = 0.f;
#pragma unroll
    for (int w = 0; w < 8; w++) Zt += expf(s_m[w] - mstar) * s_Z[w];
    float ew = expf(m - mstar);

#pragma unroll
    for (int j = 0; j < 6; j++) {
        float4 v;
        v.x = ew * acc[j].x; v.y = ew * acc[j].y;
        v.z = ew * acc[j].z; v.w = ew * acc[j].w;
        *(float4*)&s_buf[warp][4 * lane + 128 * j] = v;
    }
    __syncthreads();

    float invZ = 1.f / Zt;

    float a0 = 0.f, a1 = 0.f, a2 = 0.f;
#pragma unroll
    for (int w = 0; w < 8; w++) {
        a0 += s_buf[w][t];
        a1 += s_buf[w][t + 256];
        a2 += s_buf[w][t + 512];
    }

    float h0 = a0 * invZ + hidden[(size_t)row * DD + t]       + gat_bias[t];
    float h1 = a1 * invZ + hidden[(size_t)row * DD + t + 256] + gat_bias[t + 256];
    float h2 = a2 * invZ + hidden[(size_t)row * DD + t + 512] + gat_bias[t + 512];
    h0 = h0 > 0.f ? h0 : 0.01f * h0;
    h1 = h1 > 0.f ? h1 : 0.01f * h1;
    h2 = h2 > 0.f ? h2 : 0.01f * h2;
    g_h[(size_t)row * DD + t]       = h0;
    g_h[(size_t)row * DD + t + 256] = h1;
    g_h[(size_t)row * DD + t + 512] = h2;

    float gp = h0 * gate_W[t] + h1 * gate_W[t + 256] + h2 * gate_W[t + 512];
#pragma unroll
    for (int o = 16; o > 0; o >>= 1) gp += __shfl_xor_sync(0xffffffffu, gp, o);
    __syncthreads();
    if (lane == 0) red8[warp] = gp;
    __syncthreads();
    if (t == 0) {
        float logit = red8[0] + red8[1] + red8[2] + red8[3]
                    + red8[4] + red8[5] + red8[6] + red8[7] + gate_b[0];
        g_gate[row] = logit;
        atomicMax(&g_gmax[b], fenc(logit));
    }
}

// ============================================================
// Pool: unnormalized exp-weighted partial sums + partial Z.
// ============================================================
__global__ __launch_bounds__(256) void pool_kernel() {
    int b = blockIdx.y, s = blockIdx.x, t = threadIdx.x;
    float gmax = fdec(g_gmax[b]);
    float a0 = 0.f, a1 = 0.f, a2 = 0.f, z = 0.f;
    int l0 = s * (LL / NSPLIT);
#pragma unroll
    for (int l = l0; l < l0 + (LL / NSPLIT); l++) {
        float e = expf(g_gate[b * LL + l] - gmax);
        const float* hr = &g_h[(size_t)(b * LL + l) * DD];
        a0 += e * hr[t];
        a1 += e * hr[t + 256];
        a2 += e * hr[t + 512];
        z += e;
    }
    float* o = &g_part[(size_t)(b * NSPLIT + s) * DD];
    o[t] = a0; o[t + 256] = a1; o[t + 512] = a2;
    if (t == 0) g_partz[b * NSPLIT + s] = z;
}

// ============================================================
// Head: merge partials, /Z, relu, LN, FC, LN2.
// ============================================================
__device__ __forceinline__ float bsum(float v, float* red, int t, int n) {
    red[t] = v;
    __syncthreads();
#pragma unroll
    for (int s = 256; s > 0; s >>= 1) {
        if (t < s && t + s < n) red[t] += red[t + s];
        __syncthreads();
    }
    float r = red[0];
    __syncthreads();
    return r;
}

__global__ __launch_bounds__(DOUT) void head_kernel(
    const float* __restrict__ ln_g, const float* __restrict__ ln_b,
    const float* __restrict__ fc_W, const float* __restrict__ fc_b,
    const float* __restrict__ ln2_g, const float* __restrict__ ln2_b,
    float* __restrict__ out) {
    __shared__ float xn[DD];
    __shared__ float red[DOUT];
    int b = blockIdx.x, t = threadIdx.x;

    float Zt = 0.f;
    for (int s = 0; s < NSPLIT; s++) Zt += g_partz[b * NSPLIT + s];
    float invZ = 1.f / Zt;

    float x0 = 0.f, x1 = 0.f;
    for (int s = 0; s < NSPLIT; s++) {
        const float* pp = &g_part[(size_t)(b * NSPLIT + s) * DD];
        x0 += pp[t];
        x1 += pp[t + DOUT];
    }
    x0 = fmaxf(x0 * invZ, 0.f);
    x1 = fmaxf(x1 * invZ, 0.f);

    float mu  = bsum(x0 + x1, red, t, DOUT) * (1.f / DD);
    float q   = bsum(x0 * x0 + x1 * x1, red, t, DOUT) * (1.f / DD);
    float var = q - mu * mu;
    float rstd = rsqrtf(var + 1e-5f);
    xn[t]        = (x0 - mu) * rstd * ln_g[t] + ln_b[t];
    xn[t + DOUT] = (x1 - mu) * rstd * ln_g[t + DOUT] + ln_b[t + DOUT];
    __syncthreads();

    float o = fc_b[t];
#pragma unroll 4
    for (int d = 0; d < DD; d++) o += xn[d] * fc_W[d * DOUT + t];

    float mu2  = bsum(o, red, t, DOUT) * (1.f / DOUT);
    float q2   = bsum(o * o, red, t, DOUT) * (1.f / DOUT);
    float var2 = q2 - mu2 * mu2;
    out[b * DOUT + t] = (o - mu2) * rsqrtf(var2 + 1e-5f) * ln2_g[t] + ln2_b[t];
}

// ============================================================
extern "C" void kernel_launch(void* const* d_in, const int* in_sizes, int n_in,
                              void* d_out, int out_size) {
    const float* hidden = (const float*)d_in[0];
    const float* attn   = (const float*)d_in[1];
    const float* Wsrc   = (const float*)d_in[2];
    const float* bsrc   = (const float*)d_in[3];
    const float* Wdst   = (const float*)d_in[4];
    const float* bdst   = (const float*)d_in[5];
    const float* av     = (const float*)d_in[6];
    const float* gb     = (const float*)d_in[7];
    const float* gateW  = (const float*)d_in[8];
    const float* gateb  = (const float*)d_in[9];
    const float* lng    = (const float*)d_in[10];
    const float* lnb    = (const float*)d_in[11];
    const float* fcW    = (const float*)d_in[12];
    const float* fcb    = (const float*)d_in[13];
    const float* ln2g   = (const float*)d_in[14];
    const float* ln2b   = (const float*)d_in[15];
    float* out = (float*)d_out;

    cudaFuncSetAttribute(gemm_topk_kernel,
                         cudaFuncAttributeMaxDynamicSharedMemorySize, GEMM_SMEM);

    gemm_topk_kernel<<<GEMM_BLOCKS + NROW, 256, GEMM_SMEM>>>(
        hidden, Wsrc, bsrc, Wdst, bdst, attn);
    edge_kernel<<<NROW, 256>>>(attn, hidden, av, gb, gateW, gateb);
    pool_kernel<<<dim3(NSPLIT, BB), 256>>>();
    head_kernel<<<BB, DOUT>>>(lng, lnb, fcW, fcb, ln2g, ln2b, out);
}

// round 17
// speedup vs baseline: 1.7054x; 1.7054x over previous
#include <cuda_runtime.h>
#include <cstdint>

#define BB 4
#define LL 512
#define DD 768
#define DOUT 384
#define KSEL 51
#define NROW (BB*LL)
#define NSPLIT 64

// ---- device scratch ----
__device__ float g_fsrc[NROW * DD];
__device__ float g_fdst[NROW * DD];
__device__ float g_h[NROW * DD];
__device__ int   g_idx[NROW * KSEL];
__device__ float g_gate[NROW];
__device__ unsigned g_gmax[BB];
__device__ float g_part[BB * NSPLIT * DD];
__device__ float g_partz[BB * NSPLIT];

__device__ __forceinline__ unsigned fenc(float f) {
    unsigned u = __float_as_uint(f);
    return (u & 0x80000000u) ? ~u : (u | 0x80000000u);
}
__device__ __forceinline__ float fdec(unsigned u) {
    unsigned b = (u & 0x80000000u) ? (u & 0x7FFFFFFFu) : ~u;
    return __uint_as_float(b);
}

// ============================================================
// 1) Top-K radix select (4x8-bit rounds), warp-level suffix scan.
// ============================================================
__global__ __launch_bounds__(512) void topk_kernel(const float* __restrict__ attn) {
    __shared__ unsigned su[LL];
    __shared__ int hist[256];
    __shared__ int suf[256];
    __shared__ unsigned s_prefix;
    __shared__ int s_need;
    __shared__ int s_cnt;

    int row = blockIdx.x;
    int t = threadIdx.x;
    if (row < BB && t == 0) g_gmax[row] = 0u;
    unsigned u = __float_as_uint(attn[(size_t)row * LL + t]);
    su[t] = u;
    if (t == 0) { s_prefix = 0u; s_need = KSEL; s_cnt = 0; }
    unsigned himask = 0u;
    __syncthreads();

#pragma unroll
    for (int shift = 24; shift >= 0; shift -= 8) {
        unsigned pref = s_prefix;
        int need = s_need;
        if (t < 256) hist[t] = 0;
        __syncthreads();

        if ((u & himask) == pref) atomicAdd(&hist[(u >> shift) & 0xFF], 1);
        __syncthreads();

        if (t < 32) {
            int v[8];
            int base = t * 8;
            int sum = 0;
#pragma unroll
            for (int i = 7; i >= 0; i--) { sum += hist[base + i]; v[i] = sum; }
            int x = sum;
#pragma unroll
            for (int off = 1; off < 32; off <<= 1) {
                int y = __shfl_down_sync(0xffffffffu, x, off);
                if (t + off < 32) x += y;
            }
            int excl = x - sum;
#pragma unroll
            for (int i = 0; i < 8; i++) suf[base + i] = v[i] + excl;
        }
        __syncthreads();
        if (t < 256) {
            int above = (t + 1 < 256) ? suf[t + 1] : 0;
            if (suf[t] >= need && above < need) {
                s_need = need - above;
                s_prefix = pref | ((unsigned)t << shift);
            }
        }
        himask |= (0xFFu << shift);
        __syncthreads();
    }

    unsigned T = s_prefix;
    int need = s_need;
    if (u > T) {
        int slot = atomicAdd(&s_cnt, 1);
        g_idx[row * KSEL + slot] = t;
    }
    __syncthreads();
    int ngt = s_cnt;
    if (u == T) {
        int r = 0;
        for (int j = 0; j < t; j++) r += (su[j] == T);
        if (r < need) g_idx[row * KSEL + ngt + r] = t;
    }
}

// ============================================================
// 2) tf32 GEMM, cp.async 3-stage pipeline, BM=128 BN=64 BK=32
//    (round-10/15 proven version).
// ============================================================
#define GNIT 24
#define SA_ST 4608
#define SB_ST 2304
#define GEMM_SMEM ((3*SA_ST + 3*SB_ST) * 4)

__device__ __forceinline__ void cp16(float* sdst, const float* gsrc) {
    uint32_t s = (uint32_t)__cvta_generic_to_shared(sdst);
    asm volatile("cp.async.cg.shared.global [%0], [%1], 16;\n" :: "r"(s), "l"(gsrc));
}
__device__ __forceinline__ void mma_tf32(float* d, const uint32_t* a, const uint32_t* b) {
    asm volatile(
        "mma.sync.aligned.m16n8k8.row.col.f32.tf32.tf32.f32 "
        "{%0,%1,%2,%3}, {%4,%5,%6,%7}, {%8,%9}, {%0,%1,%2,%3};\n"
        : "+f"(d[0]), "+f"(d[1]), "+f"(d[2]), "+f"(d[3])
        : "r"(a[0]), "r"(a[1]), "r"(a[2]), "r"(a[3]), "r"(b[0]), "r"(b[1]));
}

__global__ __launch_bounds__(256) void gemm_tf32_kernel(
    const float* __restrict__ A,
    const float* __restrict__ Wsrc, const float* __restrict__ bsrc,
    const float* __restrict__ Wdst, const float* __restrict__ bdst) {
    extern __shared__ float gsm[];
    float* sAp = gsm;
    float* sBp = gsm + 3 * SA_ST;

    int tid = threadIdx.x;
    int colBase = blockIdx.x * 64;
    int rowBase = blockIdx.y * 128;

    const float *W, *bias;
    float* Cout;
    int cb;
    if (colBase < DD) { W = Wsrc; bias = bsrc; Cout = g_fsrc; cb = colBase; }
    else              { W = Wdst; bias = bdst; Cout = g_fdst; cb = colBase - DD; }

    int lane = tid & 31, wid = tid >> 5;
    int warpM = wid & 3, warpN = wid >> 2;
    int g = lane >> 2, t4 = lane & 3;

    int ar[4], ac[4];
#pragma unroll
    for (int q = 0; q < 4; q++) { int i = tid + q * 256; ar[q] = i >> 3; ac[q] = (i & 7) * 4; }
    int br[2], bc[2];
#pragma unroll
    for (int q = 0; q < 2; q++) { int i = tid + q * 256; br[q] = i >> 4; bc[q] = (i & 15) * 4; }

    float acc[2][4][4];
#pragma unroll
    for (int i = 0; i < 2; i++)
#pragma unroll
        for (int j = 0; j < 4; j++)
#pragma unroll
            for (int q = 0; q < 4; q++) acc[i][j][q] = 0.f;

#define GISSUE(it)                                                              \
    do {                                                                        \
        if ((it) < GNIT) {                                                      \
            int k0 = (it) * 32; int st = (it) % 3;                              \
            float* sA = sAp + st * SA_ST;                                       \
            float* sB = sBp + st * SB_ST;                                       \
            _Pragma("unroll")                                                   \
            for (int q = 0; q < 4; q++)                                         \
                cp16(&sA[ar[q] * 36 + ac[q]],                                   \
                     &A[(size_t)(rowBase + ar[q]) * DD + k0 + ac[q]]);          \
            _Pragma("unroll")                                                   \
            for (int q = 0; q < 2; q++)                                         \
                cp16(&sB[br[q] * 72 + bc[q]],                                   \
                     &W[(size_t)(k0 + br[q]) * DD + cb + bc[q]]);               \
        }                                                                       \
        asm volatile("cp.async.commit_group;\n" ::);                            \
    } while (0)

    GISSUE(0);
    GISSUE(1);

    for (int it = 0; it < GNIT; it++) {
        asm volatile("cp.async.wait_group 1;\n" ::);
        __syncthreads();
        GISSUE(it + 2);

        int st = it % 3;
        const float* sA = sAp + st * SA_ST;
        const float* sB = sBp + st * SB_ST;
#pragma unroll
        for (int kk = 0; kk < 4; kk++) {
            int kb = kk * 8;
            uint32_t af[2][4], bf[4][2];
#pragma unroll
            for (int i = 0; i < 2; i++) {
                int m0 = warpM * 32 + i * 16;
                af[i][0] = __float_as_uint(sA[(m0 + g) * 36 + kb + t4]);
                af[i][1] = __float_as_uint(sA[(m0 + g + 8) * 36 + kb + t4]);
                af[i][2] = __float_as_uint(sA[(m0 + g) * 36 + kb + t4 + 4]);
                af[i][3] = __float_as_uint(sA[(m0 + g + 8) * 36 + kb + t4 + 4]);
            }
#pragma unroll
            for (int j = 0; j < 4; j++) {
                int n0 = warpN * 32 + j * 8 + g;
                bf[j][0] = __float_as_uint(sB[(kb + t4) * 72 + n0]);
                bf[j][1] = __float_as_uint(sB[(kb + t4 + 4) * 72 + n0]);
            }
#pragma unroll
            for (int i = 0; i < 2; i++)
#pragma unroll
                for (int j = 0; j < 4; j++)
                    mma_tf32(acc[i][j], af[i], bf[j]);
        }
    }

#pragma unroll
    for (int i = 0; i < 2; i++) {
        int r0 = rowBase + warpM * 32 + i * 16 + g;
#pragma unroll
        for (int j = 0; j < 4; j++) {
            int c0 = cb + warpN * 32 + j * 8 + t4 * 2;
            float b0 = bias[c0], b1 = bias[c0 + 1];
            Cout[(size_t)r0 * DD + c0]           = acc[i][j][0] + b0;
            Cout[(size_t)r0 * DD + c0 + 1]       = acc[i][j][1] + b1;
            Cout[(size_t)(r0 + 8) * DD + c0]     = acc[i][j][2] + b0;
            Cout[(size_t)(r0 + 8) * DD + c0 + 1] = acc[i][j][3] + b1;
        }
    }
}

// ============================================================
// 3) Edge kernel: barrier-free warp-local online softmax with
//    buffered tree merge (round-15 proven version, unchanged).
// ============================================================
__global__ __launch_bounds__(256, 2) void edge_kernel(
    const float* __restrict__ attn, const float* __restrict__ hidden,
    const float* __restrict__ attn_vec, const float* __restrict__ gat_bias,
    const float* __restrict__ gate_W, const float* __restrict__ gate_b) {
    __shared__ float s_av[DD];
    __shared__ float s_buf[8][DD];
    __shared__ int   ik[KSEL];
    __shared__ float aval[KSEL];
    __shared__ float s_m[8];
    __shared__ float s_Z[8];
    __shared__ float red8[8];

    int row = blockIdx.x;
    int b = row >> 9;
    int t = threadIdx.x;
    int warp = t >> 5, lane = t & 31;

    if (t < KSEL) {
        int idx = g_idx[row * KSEL + t];
        ik[t] = idx;
        aval[t] = attn[(size_t)row * LL + idx];
    }
    s_av[t] = attn_vec[t];
    s_av[t + 256] = attn_vec[t + 256];
    s_av[t + 512] = attn_vec[t + 512];

    float4 fd[6];
#pragma unroll
    for (int j = 0; j < 6; j++)
        fd[j] = *(const float4*)&g_fdst[(size_t)row * DD + 4 * lane + 128 * j];
    __syncthreads();

    const float* fsb = &g_fsrc[(size_t)b * LL * DD];

    float m = -1e30f, Z = 0.f;
    float4 acc[6];
#pragma unroll
    for (int j = 0; j < 6; j++) acc[j] = make_float4(0.f, 0.f, 0.f, 0.f);

    float4 cf[6];
    {
        const float* fs = fsb + (size_t)ik[warp] * DD;
#pragma unroll
        for (int j = 0; j < 6; j++)
            cf[j] = *(const float4*)&fs[4 * lane + 128 * j];
    }

    for (int k = warp; k < KSEL; k += 8) {
        float4 nf[6];
        bool more = (k + 8) < KSEL;
        if (more) {
            const float* fs = fsb + (size_t)ik[k + 8] * DD;
#pragma unroll
            for (int j = 0; j < 6; j++)
                nf[j] = *(const float4*)&fs[4 * lane + 128 * j];
        }

        float p = 0.f;
#pragma unroll
        for (int j = 0; j < 6; j++) {
            float4 a = *(const float4*)&s_av[4 * lane + 128 * j];
            float x;
            x = cf[j].x + fd[j].x; x = x > 0.f ? x : 0.2f * x; p += x * a.x;
            x = cf[j].y + fd[j].y; x = x > 0.f ? x : 0.2f * x; p += x * a.y;
            x = cf[j].z + fd[j].z; x = x > 0.f ? x : 0.2f * x; p += x * a.z;
            x = cf[j].w + fd[j].w; x = x > 0.f ? x : 0.2f * x; p += x * a.w;
        }
#pragma unroll
        for (int o = 16; o > 0; o >>= 1) p += __shfl_xor_sync(0xffffffffu, p, o);
        float s = (aval[k] > 0.f) ? p : -1e9f;

        if (s <= m) {
            float e = expf(s - m);
            Z += e;
#pragma unroll
            for (int j = 0; j < 6; j++) {
                acc[j].x += e * cf[j].x; acc[j].y += e * cf[j].y;
                acc[j].z += e * cf[j].z; acc[j].w += e * cf[j].w;
            }
        } else {
            float sc = expf(m - s);
            Z = Z * sc + 1.f;
#pragma unroll
            for (int j = 0; j < 6; j++) {
                acc[j].x = acc[j].x * sc + cf[j].x; acc[j].y = acc[j].y * sc + cf[j].y;
                acc[j].z = acc[j].z * sc + cf[j].z; acc[j].w = acc[j].w * sc + cf[j].w;
            }
            m = s;
        }
        if (more) {
#pragma unroll
            for (int j = 0; j < 6; j++) cf[j] = nf[j];
        }
    }

    if (lane == 0) { s_m[warp] = m; s_Z[warp] = Z; }
    __syncthreads();

    float mstar = s_m[0];
#pragma unroll
    for (int w = 1; w < 8; w++) mstar = fmaxf(mstar, s_m[w]);
    float Zt = 0.f;
#pragma unroll
    for (int w = 0; w < 8; w++) Zt += expf(s_m[w] - mstar) * s_Z[w];
    float ew = expf(m - mstar);

#pragma unroll
    for (int j = 0; j < 6; j++) {
        float4 v;
        v.x = ew * acc[j].x; v.y = ew * acc[j].y;
        v.z = ew * acc[j].z; v.w = ew * acc[j].w;
        *(float4*)&s_buf[warp][4 * lane + 128 * j] = v;
    }
    __syncthreads();

    float invZ = 1.f / Zt;

    float a0 = 0.f, a1 = 0.f, a2 = 0.f;
#pragma unroll
    for (int w = 0; w < 8; w++) {
        a0 += s_buf[w][t];
        a1 += s_buf[w][t + 256];
        a2 += s_buf[w][t + 512];
    }

    float h0 = a0 * invZ + hidden[(size_t)row * DD + t]       + gat_bias[t];
    float h1 = a1 * invZ + hidden[(size_t)row * DD + t + 256] + gat_bias[t + 256];
    float h2 = a2 * invZ + hidden[(size_t)row * DD + t + 512] + gat_bias[t + 512];
    h0 = h0 > 0.f ? h0 : 0.01f * h0;
    h1 = h1 > 0.f ? h1 : 0.01f * h1;
    h2 = h2 > 0.f ? h2 : 0.01f * h2;
    g_h[(size_t)row * DD + t]       = h0;
    g_h[(size_t)row * DD + t + 256] = h1;
    g_h[(size_t)row * DD + t + 512] = h2;

    float gp = h0 * gate_W[t] + h1 * gate_W[t + 256] + h2 * gate_W[t + 512];
#pragma unroll
    for (int o = 16; o > 0; o >>= 1) gp += __shfl_xor_sync(0xffffffffu, gp, o);
    __syncthreads();
    if (lane == 0) red8[warp] = gp;
    __syncthreads();
    if (t == 0) {
        float logit = red8[0] + red8[1] + red8[2] + red8[3]
                    + red8[4] + red8[5] + red8[6] + red8[7] + gate_b[0];
        g_gate[row] = logit;
        atomicMax(&g_gmax[b], fenc(logit));
    }
}

// ============================================================
// 4) Pool: unnormalized exp-weighted partial sums + partial Z.
// ============================================================
__global__ __launch_bounds__(256) void pool_kernel() {
    int b = blockIdx.y, s = blockIdx.x, t = threadIdx.x;
    float gmax = fdec(g_gmax[b]);
    float a0 = 0.f, a1 = 0.f, a2 = 0.f, z = 0.f;
    int l0 = s * (LL / NSPLIT);
#pragma unroll
    for (int l = l0; l < l0 + (LL / NSPLIT); l++) {
        float e = expf(g_gate[b * LL + l] - gmax);
        const float* hr = &g_h[(size_t)(b * LL + l) * DD];
        a0 += e * hr[t];
        a1 += e * hr[t + 256];
        a2 += e * hr[t + 512];
        z += e;
    }
    float* o = &g_part[(size_t)(b * NSPLIT + s) * DD];
    o[t] = a0; o[t + 256] = a1; o[t + 512] = a2;
    if (t == 0) g_partz[b * NSPLIT + s] = z;
}

// ============================================================
// 5) Head: merge partials, /Z, relu, LN, FC, LN2.
//    CHANGE: 4-way ILP accumulator chains in the partial-merge
//    and FC loops (raises MLP; the single-chain FC loop was the
//    latency bottleneck flagged by the cold-cache ncu capture).
// ============================================================
__device__ __forceinline__ float bsum(float v, float* red, int t, int n) {
    red[t] = v;
    __syncthreads();
#pragma unroll
    for (int s = 256; s > 0; s >>= 1) {
        if (t < s && t + s < n) red[t] += red[t + s];
        __syncthreads();
    }
    float r = red[0];
    __syncthreads();
    return r;
}

__global__ __launch_bounds__(DOUT) void head_kernel(
    const float* __restrict__ ln_g, const float* __restrict__ ln_b,
    const float* __restrict__ fc_W, const float* __restrict__ fc_b,
    const float* __restrict__ ln2_g, const float* __restrict__ ln2_b,
    float* __restrict__ out) {
    __shared__ float xn[DD];
    __shared__ float red[DOUT];
    int b = blockIdx.x, t = threadIdx.x;

    float Zt = 0.f;
#pragma unroll 8
    for (int s = 0; s < NSPLIT; s++) Zt += g_partz[b * NSPLIT + s];
    float invZ = 1.f / Zt;

    // partial merge with 4 independent chains
    float x0a = 0.f, x0b = 0.f, x1a = 0.f, x1b = 0.f;
#pragma unroll 4
    for (int s = 0; s < NSPLIT; s += 2) {
        const float* pp0 = &g_part[(size_t)(b * NSPLIT + s) * DD];
        const float* pp1 = &g_part[(size_t)(b * NSPLIT + s + 1) * DD];
        x0a += pp0[t];
        x1a += pp0[t + DOUT];
        x0b += pp1[t];
        x1b += pp1[t + DOUT];
    }
    float x0 = fmaxf((x0a + x0b) * invZ, 0.f);
    float x1 = fmaxf((x1a + x1b) * invZ, 0.f);

    float mu  = bsum(x0 + x1, red, t, DOUT) * (1.f / DD);
    float q   = bsum(x0 * x0 + x1 * x1, red, t, DOUT) * (1.f / DD);
    float var = q - mu * mu;
    float rstd = rsqrtf(var + 1e-5f);
    xn[t]        = (x0 - mu) * rstd * ln_g[t] + ln_b[t];
    xn[t + DOUT] = (x1 - mu) * rstd * ln_g[t + DOUT] + ln_b[t + DOUT];
    __syncthreads();

    // FC with 4 independent accumulator chains (raises MLP 4x)
    float o0 = 0.f, o1 = 0.f, o2 = 0.f, o3 = 0.f;
#pragma unroll 8
    for (int d = 0; d < DD; d += 4) {
        o0 += xn[d]     * fc_W[(size_t)d * DOUT + t];
        o1 += xn[d + 1] * fc_W[(size_t)(d + 1) * DOUT + t];
        o2 += xn[d + 2] * fc_W[(size_t)(d + 2) * DOUT + t];
        o3 += xn[d + 3] * fc_W[(size_t)(d + 3) * DOUT + t];
    }
    float o = fc_b[t] + ((o0 + o1) + (o2 + o3));

    float mu2  = bsum(o, red, t, DOUT) * (1.f / DOUT);
    float q2   = bsum(o * o, red, t, DOUT) * (1.f / DOUT);
    float var2 = q2 - mu2 * mu2;
    out[b * DOUT + t] = (o - mu2) * rsqrtf(var2 + 1e-5f) * ln2_g[t] + ln2_b[t];
}

// ============================================================
extern "C" void kernel_launch(void* const* d_in, const int* in_sizes, int n_in,
                              void* d_out, int out_size) {
    const float* hidden = (const float*)d_in[0];
    const float* attn   = (const float*)d_in[1];
    const float* Wsrc   = (const float*)d_in[2];
    const float* bsrc   = (const float*)d_in[3];
    const float* Wdst   = (const float*)d_in[4];
    const float* bdst   = (const float*)d_in[5];
    const float* av     = (const float*)d_in[6];
    const float* gb     = (const float*)d_in[7];
    const float* gateW  = (const float*)d_in[8];
    const float* gateb  = (const float*)d_in[9];
    const float* lng    = (const float*)d_in[10];
    const float* lnb    = (const float*)d_in[11];
    const float* fcW    = (const float*)d_in[12];
    const float* fcb    = (const float*)d_in[13];
    const float* ln2g   = (const float*)d_in[14];
    const float* ln2b   = (const float*)d_in[15];
    float* out = (float*)d_out;

    cudaFuncSetAttribute(gemm_tf32_kernel,
                         cudaFuncAttributeMaxDynamicSharedMemorySize, GEMM_SMEM);

    topk_kernel<<<NROW, 512>>>(attn);
    gemm_tf32_kernel<<<dim3(24, 16), 256, GEMM_SMEM>>>(hidden, Wsrc, bsrc, Wdst, bdst);
    edge_kernel<<<NROW, 256>>>(attn, hidden, av, gb, gateW, gateb);
    pool_kernel<<<dim3(NSPLIT, BB), 256>>>();
    head_kernel<<<BB, DOUT>>>(lng, lnb, fcW, fcb, ln2g, ln2b, out);
}